// round 13
// baseline (speedup 1.0000x reference)
#include <cuda_runtime.h>
#include <cstdint>

#define N_PTS 100000
#define N_PAD 100096            // multiple of 256
#define CIN   256
#define CMID  64
#define COUT  256
#define KNB   27
#define LN_EPS 1e-6f

__device__ float  g_h  [N_PAD * CMID];            // tf32-rounded activations
__device__ float  g_h2 [N_PAD * CMID];            // tf32-rounded activations
__device__ float2 g_W2f[KNB * 64 * 32];           // W2 B-fragments (tf32)
__device__ float2 g_W1f[32 * 8 * 32];             // W1 B-fragments (tf32)
__device__ float2 g_W3f[8 * 32 * 32];             // W3 B-fragments (tf32)

#define KB_AS   (128*68)                          // floats per A buffer
#define SMEM_AB (2*KB_AS*4)                       // 69632 B -> 3 blocks/SM
#define SMEM_C  (32*68*4)                         // 8704 B  (kC A tile)

// ---- tf32 round helpers ----
__device__ __forceinline__ float tf32r(float x) {
    unsigned u;
    asm("cvt.rna.tf32.f32 %0, %1;" : "=r"(u) : "f"(x));
    return __uint_as_float(u);
}
__device__ __forceinline__ unsigned tf32b(float x) {
    unsigned u;
    asm("cvt.rna.tf32.f32 %0, %1;" : "=r"(u) : "f"(x));
    return u;
}

// ---- cp.async helpers ----
__device__ __forceinline__ void cp16(unsigned d, const void* s) {
    asm volatile("cp.async.cg.shared.global [%0], [%1], 16;" :: "r"(d), "l"(s));
}
__device__ __forceinline__ void cp_commit() { asm volatile("cp.async.commit_group;"); }
__device__ __forceinline__ void cp_wait1()  { asm volatile("cp.async.wait_group 1;"); }
__device__ __forceinline__ void cp_wait0()  { asm volatile("cp.async.wait_group 0;"); }

// ---- mma.sync m16n8k8 tf32 ----
__device__ __forceinline__ void mma_tf32(float* d, const unsigned* a, const unsigned* b) {
    asm volatile(
        "mma.sync.aligned.m16n8k8.row.col.f32.tf32.tf32.f32 "
        "{%0,%1,%2,%3}, {%4,%5,%6,%7}, {%8,%9}, {%0,%1,%2,%3};"
        : "+f"(d[0]), "+f"(d[1]), "+f"(d[2]), "+f"(d[3])
        : "r"(a[0]), "r"(a[1]), "r"(a[2]), "r"(a[3]), "r"(b[0]), "r"(b[1]));
}

// ---------------------------------------------------------------------------
// Prep: tf32 B-fragments for W1/W2/W3 (blocks 0..26=W2[k], 27=W1, 28=W3).
// ---------------------------------------------------------------------------
__global__ void __launch_bounds__(256) kPrep(const float* __restrict__ W1,
                                             const float* __restrict__ W2,
                                             const float* __restrict__ W3)
{
    const int blk = blockIdx.x, t = threadIdx.x;
    if (blk < KNB) {
        const float* src = W2 + blk * 4096;
#pragma unroll
        for (int e = t; e < 2048; e += 256) {
            int lane = e & 31, nt = (e >> 5) & 7, kc = e >> 8;
            int c0 = kc * 8 + (lane & 3);
            int d  = nt * 8 + (lane >> 2);
            g_W2f[(blk * 64 + kc * 8 + nt) * 32 + lane] =
                make_float2(tf32r(__ldg(src + c0 * 64 + d)),
                            tf32r(__ldg(src + (c0 + 4) * 64 + d)));
        }
    } else if (blk == KNB) {
        for (int e = t; e < 8192; e += 256) {
            int lane = e & 31, nt = (e >> 5) & 7, kcg = e >> 8;
            int c0 = kcg * 8 + (lane & 3);
            int d  = nt * 8 + (lane >> 2);
            g_W1f[(kcg * 8 + nt) * 32 + lane] =
                make_float2(tf32r(__ldg(W1 + c0 * 64 + d)),
                            tf32r(__ldg(W1 + (c0 + 4) * 64 + d)));
        }
    } else {
        for (int e = t; e < 8192; e += 256) {
            int lane = e & 31, nt = (e >> 5) & 31, kc = e >> 10;
            int c0 = kc * 8 + (lane & 3);
            int d  = nt * 8 + (lane >> 2);
            g_W3f[(kc * 32 + nt) * 32 + lane] =
                make_float2(tf32r(__ldg(W3 + c0 * 256 + d)),
                            tf32r(__ldg(W3 + (c0 + 4) * 256 + d)));
        }
    }
}

// ---------------------------------------------------------------------------
// Kernel A (tensor, 128 thr, 3 blocks/SM): h = relu(LN(feats @ W1)).
// Tile 128x64, K=256 in 4 chunks. A-only cp.async double buffer; B via __ldg.
// 4 warps; warp w: rows w*32..+31 (2mt x 8nt).
// ---------------------------------------------------------------------------
__global__ void __launch_bounds__(128, 3) kA(const float* __restrict__ feats,
                                             const float* __restrict__ g1v,
                                             const float* __restrict__ b1v)
{
    extern __shared__ float sm[];
    float* As = sm;                  // 2 x [128][68]

    const int t    = threadIdx.x;
    const int base = blockIdx.x * 128;
    const int lane = t & 31, w = t >> 5;
    const int qr = lane >> 2, ql = lane & 3;

    const unsigned As_s = (unsigned)__cvta_generic_to_shared(As);

    auto prefetch = [&](int ch, int buf) {
        unsigned ab = As_s + buf * (KB_AS * 4);
#pragma unroll
        for (int i = 0; i < 16; i++) {
            int u = t + 128 * i;
            int r = u >> 4, c4 = u & 15;
            int gr = base + r; if (gr >= N_PTS) gr = N_PTS - 1;
            cp16(ab + (r * 68 + c4 * 4) * 4, feats + gr * CIN + ch * 64 + c4 * 4);
        }
        cp_commit();
    };

    float d[2][8][4];
#pragma unroll
    for (int mt = 0; mt < 2; mt++)
#pragma unroll
        for (int nt = 0; nt < 8; nt++)
#pragma unroll
            for (int p = 0; p < 4; p++) d[mt][nt][p] = 0.f;

    prefetch(0, 0);
    for (int ch = 0; ch < 4; ch++) {
        const int buf = ch & 1;
        if (ch < 3) { prefetch(ch + 1, buf ^ 1); cp_wait1(); } else cp_wait0();
        __syncthreads();

        const float*  Ab = As + buf * KB_AS;
        const float2* Bg = g_W1f + ch * 2048 + lane;

#pragma unroll
        for (int kc = 0; kc < 8; kc++) {
            unsigned a[2][4];
#pragma unroll
            for (int mt = 0; mt < 2; mt++) {
                int r0 = w * 32 + mt * 16 + qr;
                int c0 = kc * 8 + ql;
                a[mt][0] = tf32b(Ab[r0 * 68 + c0]);
                a[mt][1] = tf32b(Ab[(r0 + 8) * 68 + c0]);
                a[mt][2] = tf32b(Ab[r0 * 68 + c0 + 4]);
                a[mt][3] = tf32b(Ab[(r0 + 8) * 68 + c0 + 4]);
            }
#pragma unroll
            for (int nt = 0; nt < 8; nt++) {
                float2 bv = __ldg(Bg + (kc * 8 + nt) * 32);
                unsigned b[2] = {__float_as_uint(bv.x), __float_as_uint(bv.y)};
                mma_tf32(d[0][nt], a[0], b);
                mma_tf32(d[1][nt], a[1], b);
            }
        }
        __syncthreads();
    }

    float2 lg[8], lb[8];
#pragma unroll
    for (int nt = 0; nt < 8; nt++) {
        lg[nt] = __ldg((const float2*)(g1v + nt * 8 + 2 * ql));
        lb[nt] = __ldg((const float2*)(b1v + nt * 8 + 2 * ql));
    }

#pragma unroll
    for (int mt = 0; mt < 2; mt++) {
#pragma unroll
        for (int h = 0; h < 2; h++) {
            int row = w * 32 + mt * 16 + qr + 8 * h;
            float s = 0.f, q = 0.f;
#pragma unroll
            for (int nt = 0; nt < 8; nt++) {
                float v0 = d[mt][nt][2 * h], v1 = d[mt][nt][2 * h + 1];
                s += v0 + v1; q += v0 * v0 + v1 * v1;
            }
            s += __shfl_xor_sync(0xffffffffu, s, 1, 4);
            q += __shfl_xor_sync(0xffffffffu, q, 1, 4);
            s += __shfl_xor_sync(0xffffffffu, s, 2, 4);
            q += __shfl_xor_sync(0xffffffffu, q, 2, 4);
            float mu  = s * (1.f / 64.f);
            float var = q * (1.f / 64.f) - mu * mu;
            float inv = rsqrtf(var + LN_EPS);

            float* dst = g_h + (base + row) * CMID + 2 * ql;   // padded
#pragma unroll
            for (int nt = 0; nt < 8; nt++) {
                float2 o;
                o.x = tf32r(fmaxf((d[mt][nt][2 * h]     - mu) * inv * lg[nt].x + lb[nt].x, 0.f));
                o.y = tf32r(fmaxf((d[mt][nt][2 * h + 1] - mu) * inv * lg[nt].y + lb[nt].y, 0.f));
                *(float2*)(dst + nt * 8) = o;
            }
        }
    }
}

// ---------------------------------------------------------------------------
// Kernel B (tensor, 128 thr, 3 blocks/SM): h2 = relu(LN(sum_k gather @ W2[k])).
// Tile 128 rows, 27 k-steps. A-only cp.async double buffer; B via __ldg.
// ---------------------------------------------------------------------------
__global__ void __launch_bounds__(128, 3) kB(const int*   __restrict__ nidx,
                                             const float* __restrict__ g2v,
                                             const float* __restrict__ b2v)
{
    extern __shared__ float sm[];
    float* As = sm;                  // 2 x [128][68]

    const int t    = threadIdx.x;
    const int base = blockIdx.x * 128;
    const int lane = t & 31, w = t >> 5;
    const int qr = lane >> 2, ql = lane & 3;

    const unsigned As_s = (unsigned)__cvta_generic_to_shared(As);

    auto prefetch = [&](int k, int buf) {
        unsigned ab = As_s + buf * (KB_AS * 4);
#pragma unroll
        for (int i = 0; i < 16; i++) {
            int u = t + 128 * i;
            int r = u >> 4, c4 = u & 15;
            int gr = base + r;
            int src = (gr < N_PTS) ? __ldg(nidx + gr * KNB + k) : 0;
            cp16(ab + (r * 68 + c4 * 4) * 4, g_h + src * CMID + c4 * 4);
        }
        cp_commit();
    };

    float d[2][8][4];
#pragma unroll
    for (int mt = 0; mt < 2; mt++)
#pragma unroll
        for (int nt = 0; nt < 8; nt++)
#pragma unroll
            for (int p = 0; p < 4; p++) d[mt][nt][p] = 0.f;

    prefetch(0, 0);
    for (int k = 0; k < KNB; k++) {
        const int buf = k & 1;
        if (k < KNB - 1) { prefetch(k + 1, buf ^ 1); cp_wait1(); } else cp_wait0();
        __syncthreads();

        const unsigned* Ab = (const unsigned*)(As + buf * KB_AS);
        const float2*   Bg = g_W2f + k * 2048 + lane;

#pragma unroll
        for (int kc = 0; kc < 8; kc++) {
            unsigned a[2][4];
#pragma unroll
            for (int mt = 0; mt < 2; mt++) {
                int r0 = w * 32 + mt * 16 + qr;
                int c0 = kc * 8 + ql;
                a[mt][0] = Ab[r0 * 68 + c0];
                a[mt][1] = Ab[(r0 + 8) * 68 + c0];
                a[mt][2] = Ab[r0 * 68 + c0 + 4];
                a[mt][3] = Ab[(r0 + 8) * 68 + c0 + 4];
            }
#pragma unroll
            for (int nt = 0; nt < 8; nt++) {
                float2 bv = __ldg(Bg + (kc * 8 + nt) * 32);
                unsigned b[2] = {__float_as_uint(bv.x), __float_as_uint(bv.y)};
                mma_tf32(d[0][nt], a[0], b);
                mma_tf32(d[1][nt], a[1], b);
            }
        }
        __syncthreads();
    }

    float2 lg[8], lb[8];
#pragma unroll
    for (int nt = 0; nt < 8; nt++) {
        lg[nt] = __ldg((const float2*)(g2v + nt * 8 + 2 * ql));
        lb[nt] = __ldg((const float2*)(b2v + nt * 8 + 2 * ql));
    }

#pragma unroll
    for (int mt = 0; mt < 2; mt++) {
#pragma unroll
        for (int h = 0; h < 2; h++) {
            int row = w * 32 + mt * 16 + qr + 8 * h;
            float s = 0.f, q = 0.f;
#pragma unroll
            for (int nt = 0; nt < 8; nt++) {
                float v0 = d[mt][nt][2 * h], v1 = d[mt][nt][2 * h + 1];
                s += v0 + v1; q += v0 * v0 + v1 * v1;
            }
            s += __shfl_xor_sync(0xffffffffu, s, 1, 4);
            q += __shfl_xor_sync(0xffffffffu, q, 1, 4);
            s += __shfl_xor_sync(0xffffffffu, s, 2, 4);
            q += __shfl_xor_sync(0xffffffffu, q, 2, 4);
            float mu  = s * (1.f / 64.f);
            float var = q * (1.f / 64.f) - mu * mu;
            float inv = rsqrtf(var + LN_EPS);

            float* dst = g_h2 + (base + row) * CMID + 2 * ql;   // padded
#pragma unroll
            for (int nt = 0; nt < 8; nt++) {
                float2 o;
                o.x = tf32r(fmaxf((d[mt][nt][2 * h]     - mu) * inv * lg[nt].x + lb[nt].x, 0.f));
                o.y = tf32r(fmaxf((d[mt][nt][2 * h + 1] - mu) * inv * lg[nt].y + lb[nt].y, 0.f));
                *(float2*)(dst + nt * 8) = o;
            }
        }
    }
}

// ---------------------------------------------------------------------------
// Kernel C (tensor, 128 thr, 4 blocks/SM): out = relu(LN(h2 @ W3) + feats)
// Tile 32 rows x 256 cols, K=64. 4 warps; warp w: cols w*64..+63 (2mt x 8nt).
// W3 fragments via __ldg (L1-resident); smem = A tile only.
// ---------------------------------------------------------------------------
__global__ void __launch_bounds__(128, 4) kC(const float* __restrict__ feats,
                                             const float* __restrict__ g3v,
                                             const float* __restrict__ b3v,
                                             float* __restrict__ out)
{
    extern __shared__ float sm[];
    float* hs = sm;                 // [32][68]

    const int t    = threadIdx.x;
    const int base = blockIdx.x * 32;
    const int lane = t & 31, w = t >> 5;     // w = col-group 0..3 (64 cols each)
    const int qr = lane >> 2, ql = lane & 3;

    // Stage A (g_h2 padded, no guard): 512 float4
#pragma unroll
    for (int i = 0; i < 4; i++) {
        int u = t + 128 * i;
        int r = u >> 4, c4 = u & 15;
        float4 v = *(const float4*)(g_h2 + (base + r) * CMID + c4 * 4);
        *(float4*)&hs[r * 68 + c4 * 4] = v;
    }
    __syncthreads();

    float d[2][8][4];
#pragma unroll
    for (int mt = 0; mt < 2; mt++)
#pragma unroll
        for (int nt = 0; nt < 8; nt++)
#pragma unroll
            for (int p = 0; p < 4; p++) d[mt][nt][p] = 0.f;

    const unsigned* Ab = (const unsigned*)hs;
    const float2*   Bg = g_W3f + w * 8 * 32 + lane;   // (kc*32 + w*8 + nt)*32

#pragma unroll
    for (int kc = 0; kc < 8; kc++) {
        unsigned a[2][4];
#pragma unroll
        for (int mt = 0; mt < 2; mt++) {
            int r0 = mt * 16 + qr;
            int c0 = kc * 8 + ql;
            a[mt][0] = Ab[r0 * 68 + c0];
            a[mt][1] = Ab[(r0 + 8) * 68 + c0];
            a[mt][2] = Ab[r0 * 68 + c0 + 4];
            a[mt][3] = Ab[(r0 + 8) * 68 + c0 + 4];
        }
#pragma unroll
        for (int nt = 0; nt < 8; nt++) {
            float2 bv = __ldg(Bg + (kc * 32 + nt) * 32);
            unsigned b[2] = {__float_as_uint(bv.x), __float_as_uint(bv.y)};
            mma_tf32(d[0][nt], a[0], b);
            mma_tf32(d[1][nt], a[1], b);
        }
    }

    // LN over 256 cols: quad partials -> smem [32][4] -> combine
    __syncthreads();
    float2* red = (float2*)hs;      // reuse (32*4 float2 = 1KB)
#pragma unroll
    for (int mt = 0; mt < 2; mt++) {
#pragma unroll
        for (int h = 0; h < 2; h++) {
            int row = mt * 16 + qr + 8 * h;
            float s = 0.f, q = 0.f;
#pragma unroll
            for (int nt = 0; nt < 8; nt++) {
                float v0 = d[mt][nt][2 * h], v1 = d[mt][nt][2 * h + 1];
                s += v0 + v1; q += v0 * v0 + v1 * v1;
            }
            s += __shfl_xor_sync(0xffffffffu, s, 1, 4);
            q += __shfl_xor_sync(0xffffffffu, q, 1, 4);
            s += __shfl_xor_sync(0xffffffffu, s, 2, 4);
            q += __shfl_xor_sync(0xffffffffu, q, 2, 4);
            if (ql == 0) red[row * 4 + w] = make_float2(s, q);
        }
    }
    __syncthreads();

#pragma unroll
    for (int mt = 0; mt < 2; mt++) {
#pragma unroll
        for (int h = 0; h < 2; h++) {
            int row  = mt * 16 + qr + 8 * h;
            int grow = base + row;
            float2 p0 = red[row * 4 + 0], p1 = red[row * 4 + 1];
            float2 p2 = red[row * 4 + 2], p3 = red[row * 4 + 3];
            float S = p0.x + p1.x + p2.x + p3.x;
            float Q = p0.y + p1.y + p2.y + p3.y;
            float mu  = S * (1.f / 256.f);
            float var = Q * (1.f / 256.f) - mu * mu;
            float inv = rsqrtf(var + LN_EPS);

            if (grow < N_PTS) {
                const float* fsrc = feats + grow * CIN + w * 64 + 2 * ql;
                float* dst = out + grow * COUT + w * 64 + 2 * ql;
#pragma unroll
                for (int nt = 0; nt < 8; nt++) {
                    float2 gg = __ldg((const float2*)(g3v + w * 64 + nt * 8 + 2 * ql));
                    float2 bb = __ldg((const float2*)(b3v + w * 64 + nt * 8 + 2 * ql));
                    float2 r4 = __ldg((const float2*)(fsrc + nt * 8));
                    float2 o;
                    o.x = fmaxf((d[mt][nt][2 * h]     - mu) * inv * gg.x + bb.x + r4.x, 0.f);
                    o.y = fmaxf((d[mt][nt][2 * h + 1] - mu) * inv * gg.y + bb.y + r4.y, 0.f);
                    *(float2*)(dst + nt * 8) = o;
                }
            }
        }
    }
}

// ---------------------------------------------------------------------------
extern "C" void kernel_launch(void* const* d_in, const int* in_sizes, int n_in,
                              void* d_out, int out_size)
{
    const float* feats = (const float*)d_in[0];
    const int*   nidx  = (const int*)  d_in[1];
    const float* W1    = (const float*)d_in[2];
    const float* g1    = (const float*)d_in[3];
    const float* b1    = (const float*)d_in[4];
    const float* W2    = (const float*)d_in[5];
    const float* g2    = (const float*)d_in[6];
    const float* b2    = (const float*)d_in[7];
    const float* W3    = (const float*)d_in[8];
    const float* g3    = (const float*)d_in[9];
    const float* b3    = (const float*)d_in[10];
    float* out = (float*)d_out;

    cudaFuncSetAttribute(kA, cudaFuncAttributeMaxDynamicSharedMemorySize, SMEM_AB);
    cudaFuncSetAttribute(kB, cudaFuncAttributeMaxDynamicSharedMemorySize, SMEM_AB);
    cudaFuncSetAttribute(kC, cudaFuncAttributeMaxDynamicSharedMemorySize, SMEM_C);

    kPrep<<<KNB + 2, 256>>>(W1, W2, W3);
    kA<<<N_PAD / 128, 128, SMEM_AB>>>(feats, g1, b1);
    kB<<<N_PAD / 128, 128, SMEM_AB>>>(nidx, g2, b2);
    kC<<<N_PAD / 32, 128, SMEM_C>>>(feats, g3, b3, out);
}

// round 14
// speedup vs baseline: 1.6003x; 1.6003x over previous
#include <cuda_runtime.h>
#include <cstdint>

#define N_PTS 100000
#define N_PAD 100096            // multiple of 256
#define CIN   256
#define CMID  64
#define COUT  256
#define KNB   27
#define LN_EPS 1e-6f

__device__ float  g_h  [N_PAD * CMID];            // tf32-rounded activations
__device__ float  g_h2 [N_PAD * CMID];            // tf32-rounded activations
__device__ float2 g_W2f[KNB * 64 * 32];           // W2 B-fragments (tf32)
__device__ float2 g_W1f[32 * 8 * 32];             // W1 B-fragments (tf32)
__device__ float2 g_W3f[8 * 32 * 32];             // W3 B-fragments (tf32)

#define KB_AS   (128*68)                          // floats per A buffer
#define KB_BS   4096                              // floats per B buffer (16KB)
#define SMEM_AB ((2*KB_AS + 2*KB_BS) * 4)         // 102400 B -> 2 blocks/SM
#define KC_AS   (64*68)                           // floats per kC A buffer
#define SMEM_C  ((2*KC_AS + 16384) * 4 + 2048)    // 102400 B -> 2 blocks/SM
#define KC_TILES ((N_PAD + 63) / 64)              // 1564
#define KC_GRID  296

// ---- tf32 round helpers ----
__device__ __forceinline__ float tf32r(float x) {
    unsigned u;
    asm("cvt.rna.tf32.f32 %0, %1;" : "=r"(u) : "f"(x));
    return __uint_as_float(u);
}
__device__ __forceinline__ unsigned tf32b(float x) {
    unsigned u;
    asm("cvt.rna.tf32.f32 %0, %1;" : "=r"(u) : "f"(x));
    return u;
}

// ---- cp.async helpers ----
__device__ __forceinline__ void cp16(unsigned d, const void* s) {
    asm volatile("cp.async.cg.shared.global [%0], [%1], 16;" :: "r"(d), "l"(s));
}
__device__ __forceinline__ void cp_commit() { asm volatile("cp.async.commit_group;"); }
__device__ __forceinline__ void cp_wait1()  { asm volatile("cp.async.wait_group 1;"); }
__device__ __forceinline__ void cp_wait0()  { asm volatile("cp.async.wait_group 0;"); }

// ---- mma.sync m16n8k8 tf32 ----
__device__ __forceinline__ void mma_tf32(float* d, const unsigned* a, const unsigned* b) {
    asm volatile(
        "mma.sync.aligned.m16n8k8.row.col.f32.tf32.tf32.f32 "
        "{%0,%1,%2,%3}, {%4,%5,%6,%7}, {%8,%9}, {%0,%1,%2,%3};"
        : "+f"(d[0]), "+f"(d[1]), "+f"(d[2]), "+f"(d[3])
        : "r"(a[0]), "r"(a[1]), "r"(a[2]), "r"(a[3]), "r"(b[0]), "r"(b[1]));
}

// ---------------------------------------------------------------------------
// Prep: tf32 B-fragments for W1/W2/W3 (blocks 0..26=W2[k], 27=W1, 28=W3).
// ---------------------------------------------------------------------------
__global__ void __launch_bounds__(256) kPrep(const float* __restrict__ W1,
                                             const float* __restrict__ W2,
                                             const float* __restrict__ W3)
{
    const int blk = blockIdx.x, t = threadIdx.x;
    if (blk < KNB) {
        const float* src = W2 + blk * 4096;
#pragma unroll
        for (int e = t; e < 2048; e += 256) {
            int lane = e & 31, nt = (e >> 5) & 7, kc = e >> 8;
            int c0 = kc * 8 + (lane & 3);
            int d  = nt * 8 + (lane >> 2);
            g_W2f[(blk * 64 + kc * 8 + nt) * 32 + lane] =
                make_float2(tf32r(__ldg(src + c0 * 64 + d)),
                            tf32r(__ldg(src + (c0 + 4) * 64 + d)));
        }
    } else if (blk == KNB) {
        for (int e = t; e < 8192; e += 256) {
            int lane = e & 31, nt = (e >> 5) & 7, kcg = e >> 8;
            int c0 = kcg * 8 + (lane & 3);
            int d  = nt * 8 + (lane >> 2);
            g_W1f[(kcg * 8 + nt) * 32 + lane] =
                make_float2(tf32r(__ldg(W1 + c0 * 64 + d)),
                            tf32r(__ldg(W1 + (c0 + 4) * 64 + d)));
        }
    } else {
        for (int e = t; e < 8192; e += 256) {
            int lane = e & 31, nt = (e >> 5) & 31, kc = e >> 10;
            int c0 = kc * 8 + (lane & 3);
            int d  = nt * 8 + (lane >> 2);
            g_W3f[(kc * 32 + nt) * 32 + lane] =
                make_float2(tf32r(__ldg(W3 + c0 * 256 + d)),
                            tf32r(__ldg(W3 + (c0 + 4) * 256 + d)));
        }
    }
}

// ---------------------------------------------------------------------------
// Kernel A (tensor, 128 thr, 2 blocks/SM — R11): h = relu(LN(feats @ W1)).
// Tile 128x64, K=256 in 4 chunks, cp.async double buffer (A + B frags).
// 4 warps; warp w: rows w*32..+31 (2 mt x 8 nt).
// ---------------------------------------------------------------------------
__global__ void __launch_bounds__(128, 2) kA(const float* __restrict__ feats,
                                             const float* __restrict__ g1v,
                                             const float* __restrict__ b1v)
{
    extern __shared__ float sm[];
    float* As = sm;                  // 2 x [128][68]
    float* Bf = sm + 2 * KB_AS;      // 2 x [4096]

    const int t    = threadIdx.x;
    const int base = blockIdx.x * 128;
    const int lane = t & 31, w = t >> 5;
    const int qr = lane >> 2, ql = lane & 3;

    const unsigned As_s = (unsigned)__cvta_generic_to_shared(As);
    const unsigned Bf_s = (unsigned)__cvta_generic_to_shared(Bf);

    auto prefetch = [&](int ch, int buf) {
        const float4* bsrc = (const float4*)(g_W1f + ch * 2048);
        unsigned bb = Bf_s + buf * (KB_BS * 4);
#pragma unroll
        for (int i = 0; i < 8; i++) {
            int u = t + 128 * i;
            cp16(bb + u * 16, bsrc + u);
        }
        unsigned ab = As_s + buf * (KB_AS * 4);
#pragma unroll
        for (int i = 0; i < 16; i++) {
            int u = t + 128 * i;
            int r = u >> 4, c4 = u & 15;
            int gr = base + r; if (gr >= N_PTS) gr = N_PTS - 1;
            cp16(ab + (r * 68 + c4 * 4) * 4, feats + gr * CIN + ch * 64 + c4 * 4);
        }
        cp_commit();
    };

    float d[2][8][4];
#pragma unroll
    for (int mt = 0; mt < 2; mt++)
#pragma unroll
        for (int nt = 0; nt < 8; nt++)
#pragma unroll
            for (int p = 0; p < 4; p++) d[mt][nt][p] = 0.f;

    prefetch(0, 0);
    for (int ch = 0; ch < 4; ch++) {
        const int buf = ch & 1;
        if (ch < 3) { prefetch(ch + 1, buf ^ 1); cp_wait1(); } else cp_wait0();
        __syncthreads();

        const float*  Ab = As + buf * KB_AS;
        const float2* Bb = (const float2*)(Bf + buf * KB_BS);

#pragma unroll
        for (int kc = 0; kc < 8; kc++) {
            unsigned a[2][4];
#pragma unroll
            for (int mt = 0; mt < 2; mt++) {
                int r0 = w * 32 + mt * 16 + qr;
                int c0 = kc * 8 + ql;
                a[mt][0] = tf32b(Ab[r0 * 68 + c0]);
                a[mt][1] = tf32b(Ab[(r0 + 8) * 68 + c0]);
                a[mt][2] = tf32b(Ab[r0 * 68 + c0 + 4]);
                a[mt][3] = tf32b(Ab[(r0 + 8) * 68 + c0 + 4]);
            }
#pragma unroll
            for (int nt = 0; nt < 8; nt++) {
                float2 bv = Bb[(kc * 8 + nt) * 32 + lane];
                unsigned b[2] = {__float_as_uint(bv.x), __float_as_uint(bv.y)};
                mma_tf32(d[0][nt], a[0], b);
                mma_tf32(d[1][nt], a[1], b);
            }
        }
        __syncthreads();
    }

    float2 lg[8], lb[8];
#pragma unroll
    for (int nt = 0; nt < 8; nt++) {
        lg[nt] = __ldg((const float2*)(g1v + nt * 8 + 2 * ql));
        lb[nt] = __ldg((const float2*)(b1v + nt * 8 + 2 * ql));
    }

#pragma unroll
    for (int mt = 0; mt < 2; mt++) {
#pragma unroll
        for (int h = 0; h < 2; h++) {
            int row = w * 32 + mt * 16 + qr + 8 * h;
            float s = 0.f, q = 0.f;
#pragma unroll
            for (int nt = 0; nt < 8; nt++) {
                float v0 = d[mt][nt][2 * h], v1 = d[mt][nt][2 * h + 1];
                s += v0 + v1; q += v0 * v0 + v1 * v1;
            }
            s += __shfl_xor_sync(0xffffffffu, s, 1, 4);
            q += __shfl_xor_sync(0xffffffffu, q, 1, 4);
            s += __shfl_xor_sync(0xffffffffu, s, 2, 4);
            q += __shfl_xor_sync(0xffffffffu, q, 2, 4);
            float mu  = s * (1.f / 64.f);
            float var = q * (1.f / 64.f) - mu * mu;
            float inv = rsqrtf(var + LN_EPS);

            float* dst = g_h + (base + row) * CMID + 2 * ql;   // padded
#pragma unroll
            for (int nt = 0; nt < 8; nt++) {
                float2 o;
                o.x = tf32r(fmaxf((d[mt][nt][2 * h]     - mu) * inv * lg[nt].x + lb[nt].x, 0.f));
                o.y = tf32r(fmaxf((d[mt][nt][2 * h + 1] - mu) * inv * lg[nt].y + lb[nt].y, 0.f));
                *(float2*)(dst + nt * 8) = o;
            }
        }
    }
}

// ---------------------------------------------------------------------------
// Kernel B (tensor, 128 thr, 2 blocks/SM — R11): h2 = relu(LN(sum_k gather @ W2[k])).
// Tile 128 rows, 27 k-steps, cp.async double buffer. Warp: 32 rows x 64 cols.
// ---------------------------------------------------------------------------
__global__ void __launch_bounds__(128, 2) kB(const int*   __restrict__ nidx,
                                             const float* __restrict__ g2v,
                                             const float* __restrict__ b2v)
{
    extern __shared__ float sm[];
    float* As = sm;                  // 2 x [128][68]
    float* Bf = sm + 2 * KB_AS;      // 2 x [4096]

    const int t    = threadIdx.x;
    const int base = blockIdx.x * 128;
    const int lane = t & 31, w = t >> 5;
    const int qr = lane >> 2, ql = lane & 3;

    const unsigned As_s = (unsigned)__cvta_generic_to_shared(As);
    const unsigned Bf_s = (unsigned)__cvta_generic_to_shared(Bf);

    auto prefetch = [&](int k, int buf) {
        const float4* bsrc = (const float4*)(g_W2f + k * 2048);
        unsigned bb = Bf_s + buf * (KB_BS * 4);
#pragma unroll
        for (int i = 0; i < 8; i++) {
            int u = t + 128 * i;
            cp16(bb + u * 16, bsrc + u);
        }
        unsigned ab = As_s + buf * (KB_AS * 4);
#pragma unroll
        for (int i = 0; i < 16; i++) {
            int u = t + 128 * i;
            int r = u >> 4, c4 = u & 15;
            int gr = base + r;
            int src = (gr < N_PTS) ? __ldg(nidx + gr * KNB + k) : 0;
            cp16(ab + (r * 68 + c4 * 4) * 4, g_h + src * CMID + c4 * 4);
        }
        cp_commit();
    };

    float d[2][8][4];
#pragma unroll
    for (int mt = 0; mt < 2; mt++)
#pragma unroll
        for (int nt = 0; nt < 8; nt++)
#pragma unroll
            for (int p = 0; p < 4; p++) d[mt][nt][p] = 0.f;

    prefetch(0, 0);
    for (int k = 0; k < KNB; k++) {
        const int buf = k & 1;
        if (k < KNB - 1) { prefetch(k + 1, buf ^ 1); cp_wait1(); } else cp_wait0();
        __syncthreads();

        const unsigned* Ab = (const unsigned*)(As + buf * KB_AS);
        const float2*   Bb = (const float2*)(Bf + buf * KB_BS);

#pragma unroll
        for (int kc = 0; kc < 8; kc++) {
            unsigned a[2][4];
#pragma unroll
            for (int mt = 0; mt < 2; mt++) {
                int r0 = w * 32 + mt * 16 + qr;
                int c0 = kc * 8 + ql;
                a[mt][0] = Ab[r0 * 68 + c0];
                a[mt][1] = Ab[(r0 + 8) * 68 + c0];
                a[mt][2] = Ab[r0 * 68 + c0 + 4];
                a[mt][3] = Ab[(r0 + 8) * 68 + c0 + 4];
            }
#pragma unroll
            for (int nt = 0; nt < 8; nt++) {
                float2 bv = Bb[(kc * 8 + nt) * 32 + lane];
                unsigned b[2] = {__float_as_uint(bv.x), __float_as_uint(bv.y)};
                mma_tf32(d[0][nt], a[0], b);
                mma_tf32(d[1][nt], a[1], b);
            }
        }
        __syncthreads();
    }

    float2 lg[8], lb[8];
#pragma unroll
    for (int nt = 0; nt < 8; nt++) {
        lg[nt] = __ldg((const float2*)(g2v + nt * 8 + 2 * ql));
        lb[nt] = __ldg((const float2*)(b2v + nt * 8 + 2 * ql));
    }

#pragma unroll
    for (int mt = 0; mt < 2; mt++) {
#pragma unroll
        for (int h = 0; h < 2; h++) {
            int row = w * 32 + mt * 16 + qr + 8 * h;
            float s = 0.f, q = 0.f;
#pragma unroll
            for (int nt = 0; nt < 8; nt++) {
                float v0 = d[mt][nt][2 * h], v1 = d[mt][nt][2 * h + 1];
                s += v0 + v1; q += v0 * v0 + v1 * v1;
            }
            s += __shfl_xor_sync(0xffffffffu, s, 1, 4);
            q += __shfl_xor_sync(0xffffffffu, q, 1, 4);
            s += __shfl_xor_sync(0xffffffffu, s, 2, 4);
            q += __shfl_xor_sync(0xffffffffu, q, 2, 4);
            float mu  = s * (1.f / 64.f);
            float var = q * (1.f / 64.f) - mu * mu;
            float inv = rsqrtf(var + LN_EPS);

            float* dst = g_h2 + (base + row) * CMID + 2 * ql;   // padded
#pragma unroll
            for (int nt = 0; nt < 8; nt++) {
                float2 o;
                o.x = tf32r(fmaxf((d[mt][nt][2 * h]     - mu) * inv * lg[nt].x + lb[nt].x, 0.f));
                o.y = tf32r(fmaxf((d[mt][nt][2 * h + 1] - mu) * inv * lg[nt].y + lb[nt].y, 0.f));
                *(float2*)(dst + nt * 8) = o;
            }
        }
    }
}

// ---------------------------------------------------------------------------
// Kernel C (tensor, PERSISTENT, 256 thr, 2 blocks/SM): out = relu(LN(h2@W3)+feats)
// Grid 296. Each block stages W3 frags (64KB) ONCE, then loops over 64-row
// tiles with a cp.async double-buffered A tile. Warp (of 8): wr=w>>2, wc=w&3.
// ---------------------------------------------------------------------------
__global__ void __launch_bounds__(256, 2) kC(const float* __restrict__ feats,
                                             const float* __restrict__ g3v,
                                             const float* __restrict__ b3v,
                                             float* __restrict__ out)
{
    extern __shared__ float sm[];
    float*  As  = sm;                       // 2 x [64][68]
    float*  Bs  = sm + 2 * KC_AS;           // [16384] W3 frags (64KB)
    float2* red = (float2*)(sm + 2 * KC_AS + 16384);  // [64][4]

    const int t    = threadIdx.x;
    const int lane = t & 31, w = t >> 5;
    const int wr = w >> 2, wc = w & 3;
    const int qr = lane >> 2, ql = lane & 3;

    const unsigned As_s = (unsigned)__cvta_generic_to_shared(As);

    // Stage W3 frags once (4096 float4 = 64KB)
#pragma unroll
    for (int i = 0; i < 16; i++) {
        int u = t + 256 * i;
        *(float4*)&Bs[u * 4] = __ldg((const float4*)g_W3f + u);
    }

    auto prefetchA = [&](int tile, int buf) {
        unsigned ab = As_s + buf * (KC_AS * 4);
        const float* src = g_h2 + tile * 64 * CMID;   // padded, always in-bounds
#pragma unroll
        for (int i = 0; i < 4; i++) {
            int u = t + 256 * i;
            int r = u >> 4, c4 = u & 15;
            cp16(ab + (r * 68 + c4 * 4) * 4, src + r * CMID + c4 * 4);
        }
        cp_commit();
    };

    float2 lg[8], lb[8];
#pragma unroll
    for (int nt = 0; nt < 8; nt++) {
        lg[nt] = __ldg((const float2*)(g3v + wc * 64 + nt * 8 + 2 * ql));
        lb[nt] = __ldg((const float2*)(b3v + wc * 64 + nt * 8 + 2 * ql));
    }

    int tile = blockIdx.x;
    prefetchA(tile, 0);
    int it = 0;
    for (; tile < KC_TILES; tile += KC_GRID, it++) {
        const int buf  = it & 1;
        const int base = tile * 64;
        int ntile = tile + KC_GRID;
        if (ntile < KC_TILES) { prefetchA(ntile, buf ^ 1); cp_wait1(); } else cp_wait0();
        __syncthreads();   // A[buf] ready for all; also orders Bs (first iter)

        const unsigned* Ab = (const unsigned*)(As + buf * KC_AS);
        const float2*   Bb = (const float2*)Bs;

        float d[2][8][4];
#pragma unroll
        for (int mt = 0; mt < 2; mt++)
#pragma unroll
            for (int nt = 0; nt < 8; nt++)
#pragma unroll
                for (int p = 0; p < 4; p++) d[mt][nt][p] = 0.f;

#pragma unroll
        for (int kc = 0; kc < 8; kc++) {
            unsigned a[2][4];
#pragma unroll
            for (int mt = 0; mt < 2; mt++) {
                int r0 = wr * 32 + mt * 16 + qr;
                int c0 = kc * 8 + ql;
                a[mt][0] = Ab[r0 * 68 + c0];
                a[mt][1] = Ab[(r0 + 8) * 68 + c0];
                a[mt][2] = Ab[r0 * 68 + c0 + 4];
                a[mt][3] = Ab[(r0 + 8) * 68 + c0 + 4];
            }
#pragma unroll
            for (int nt = 0; nt < 8; nt++) {
                float2 bv = Bb[(kc * 32 + wc * 8 + nt) * 32 + lane];
                unsigned b[2] = {__float_as_uint(bv.x), __float_as_uint(bv.y)};
                mma_tf32(d[0][nt], a[0], b);
                mma_tf32(d[1][nt], a[1], b);
            }
        }

        // LN over 256 cols: quad partials -> red[64][4] -> combine
#pragma unroll
        for (int mt = 0; mt < 2; mt++) {
#pragma unroll
            for (int h = 0; h < 2; h++) {
                int row = wr * 32 + mt * 16 + qr + 8 * h;
                float s = 0.f, q = 0.f;
#pragma unroll
                for (int nt = 0; nt < 8; nt++) {
                    float v0 = d[mt][nt][2 * h], v1 = d[mt][nt][2 * h + 1];
                    s += v0 + v1; q += v0 * v0 + v1 * v1;
                }
                s += __shfl_xor_sync(0xffffffffu, s, 1, 4);
                q += __shfl_xor_sync(0xffffffffu, q, 1, 4);
                s += __shfl_xor_sync(0xffffffffu, s, 2, 4);
                q += __shfl_xor_sync(0xffffffffu, q, 2, 4);
                if (ql == 0) red[row * 4 + wc] = make_float2(s, q);
            }
        }
        __syncthreads();

#pragma unroll
        for (int mt = 0; mt < 2; mt++) {
#pragma unroll
            for (int h = 0; h < 2; h++) {
                int row  = wr * 32 + mt * 16 + qr + 8 * h;
                int grow = base + row;
                float2 p0 = red[row * 4 + 0], p1 = red[row * 4 + 1];
                float2 p2 = red[row * 4 + 2], p3 = red[row * 4 + 3];
                float S = p0.x + p1.x + p2.x + p3.x;
                float Q = p0.y + p1.y + p2.y + p3.y;
                float mu  = S * (1.f / 256.f);
                float var = Q * (1.f / 256.f) - mu * mu;
                float inv = rsqrtf(var + LN_EPS);

                if (grow < N_PTS) {
                    const float* fsrc = feats + grow * CIN + wc * 64 + 2 * ql;
                    float* dst = out + grow * COUT + wc * 64 + 2 * ql;
#pragma unroll
                    for (int nt = 0; nt < 8; nt++) {
                        float2 r4 = __ldg((const float2*)(fsrc + nt * 8));
                        float2 o;
                        o.x = fmaxf((d[mt][nt][2 * h]     - mu) * inv * lg[nt].x + lb[nt].x + r4.x, 0.f);
                        o.y = fmaxf((d[mt][nt][2 * h + 1] - mu) * inv * lg[nt].y + lb[nt].y + r4.y, 0.f);
                        *(float2*)(dst + nt * 8) = o;
                    }
                }
            }
        }
    }
}

// ---------------------------------------------------------------------------
extern "C" void kernel_launch(void* const* d_in, const int* in_sizes, int n_in,
                              void* d_out, int out_size)
{
    const float* feats = (const float*)d_in[0];
    const int*   nidx  = (const int*)  d_in[1];
    const float* W1    = (const float*)d_in[2];
    const float* g1    = (const float*)d_in[3];
    const float* b1    = (const float*)d_in[4];
    const float* W2    = (const float*)d_in[5];
    const float* g2    = (const float*)d_in[6];
    const float* b2    = (const float*)d_in[7];
    const float* W3    = (const float*)d_in[8];
    const float* g3    = (const float*)d_in[9];
    const float* b3    = (const float*)d_in[10];
    float* out = (float*)d_out;

    cudaFuncSetAttribute(kA, cudaFuncAttributeMaxDynamicSharedMemorySize, SMEM_AB);
    cudaFuncSetAttribute(kB, cudaFuncAttributeMaxDynamicSharedMemorySize, SMEM_AB);
    cudaFuncSetAttribute(kC, cudaFuncAttributeMaxDynamicSharedMemorySize, SMEM_C);

    kPrep<<<KNB + 2, 256>>>(W1, W2, W3);
    kA<<<N_PAD / 128, 128, SMEM_AB>>>(feats, g1, b1);
    kB<<<N_PAD / 128, 128, SMEM_AB>>>(nidx, g2, b2);
    kC<<<KC_GRID, 256, SMEM_C>>>(feats, g3, b3, out);
}

// round 15
// speedup vs baseline: 2.4448x; 1.5277x over previous
#include <cuda_runtime.h>
#include <cuda_fp16.h>
#include <cstdint>

#define N_PTS 100000
#define N_PAD 100096            // multiple of 256
#define CIN   256
#define CMID  64
#define COUT  256
#define KNB   27
#define LN_EPS 1e-6f

__device__ __half g_h [N_PAD * CMID];             // fp16 activations
__device__ __half g_h2[N_PAD * CMID];             // fp16 activations
__device__ float2 g_W1f [32 * 8 * 32];            // W1 B-frags (tf32, kA)
__device__ uint2  g_W2fh[KNB * 4 * 8 * 32];       // W2 B-frags (fp16)
__device__ uint2  g_W3fh[4 * 32 * 32];            // W3 B-frags (fp16)

// kA (tf32, unchanged shapes): A fp32 [128][68] x2 + B tf32 frags x2
#define KA_AS   (128*68)
#define KA_BS   4096
#define SMEM_A  ((2*KA_AS + 2*KA_BS) * 4)         // 102400 B -> 2 blocks/SM
// kB (fp16): A u32[128][36] x2 + B uint2[1024] x2
#define KB_AW   (128*36)                          // u32 per A buffer
#define KB_BW   2048                              // u32 per B buffer
#define SMEM_B  ((2*KB_AW + 2*KB_BW) * 4)         // 53248 B -> 3 blocks/SM
// kC (fp16, persistent): A u32[64][36] x2 + W3 frags 32KB + red
#define KC_AW   (64*36)
#define SMEM_C  ((2*KC_AW + 8192) * 4 + 2048)     // 53248 B
#define KC_TILES ((N_PAD + 63) / 64)              // 1564
#define KC_GRID  296

// ---- helpers ----
__device__ __forceinline__ float tf32r(float x) {
    unsigned u; asm("cvt.rna.tf32.f32 %0, %1;" : "=r"(u) : "f"(x));
    return __uint_as_float(u);
}
__device__ __forceinline__ unsigned tf32b(float x) {
    unsigned u; asm("cvt.rna.tf32.f32 %0, %1;" : "=r"(u) : "f"(x));
    return u;
}
__device__ __forceinline__ unsigned packh(float x, float y) {
    __half2 h = __floats2half2_rn(x, y);
    return *(unsigned*)&h;
}
__device__ __forceinline__ void cp16(unsigned d, const void* s) {
    asm volatile("cp.async.cg.shared.global [%0], [%1], 16;" :: "r"(d), "l"(s));
}
__device__ __forceinline__ void cp_commit() { asm volatile("cp.async.commit_group;"); }
__device__ __forceinline__ void cp_wait1()  { asm volatile("cp.async.wait_group 1;"); }
__device__ __forceinline__ void cp_wait0()  { asm volatile("cp.async.wait_group 0;"); }

__device__ __forceinline__ void mma_tf32(float* d, const unsigned* a, const unsigned* b) {
    asm volatile(
        "mma.sync.aligned.m16n8k8.row.col.f32.tf32.tf32.f32 "
        "{%0,%1,%2,%3}, {%4,%5,%6,%7}, {%8,%9}, {%0,%1,%2,%3};"
        : "+f"(d[0]), "+f"(d[1]), "+f"(d[2]), "+f"(d[3])
        : "r"(a[0]), "r"(a[1]), "r"(a[2]), "r"(a[3]), "r"(b[0]), "r"(b[1]));
}
__device__ __forceinline__ void mma_f16(float* d, const unsigned* a, const unsigned* b) {
    asm volatile(
        "mma.sync.aligned.m16n8k16.row.col.f32.f16.f16.f32 "
        "{%0,%1,%2,%3}, {%4,%5,%6,%7}, {%8,%9}, {%0,%1,%2,%3};"
        : "+f"(d[0]), "+f"(d[1]), "+f"(d[2]), "+f"(d[3])
        : "r"(a[0]), "r"(a[1]), "r"(a[2]), "r"(a[3]), "r"(b[0]), "r"(b[1]));
}

// ---------------------------------------------------------------------------
// Prep. blocks 0..26: W2[k] fp16 frags. block 27: W1 tf32 frags. block 28: W3 fp16.
// fp16 frag (kc,nt), lane(qr,ql): b0={W[kc*16+2ql][n], W[..+1][n]},
// b1={W[kc*16+2ql+8][n], W[..+9][n]}, n = nt*8+qr.
// ---------------------------------------------------------------------------
__global__ void __launch_bounds__(256) kPrep(const float* __restrict__ W1,
                                             const float* __restrict__ W2,
                                             const float* __restrict__ W3)
{
    const int blk = blockIdx.x, t = threadIdx.x;
    if (blk < KNB) {
        const float* src = W2 + blk * 4096;   // [64][64]
#pragma unroll
        for (int e = t; e < 1024; e += 256) {
            int lane = e & 31, nt = (e >> 5) & 7, kc = e >> 8;
            int qr = lane >> 2, ql = lane & 3;
            int n  = nt * 8 + qr;
            int c0 = kc * 16 + 2 * ql;
            uint2 v;
            v.x = packh(src[c0 * 64 + n],       src[(c0 + 1) * 64 + n]);
            v.y = packh(src[(c0 + 8) * 64 + n], src[(c0 + 9) * 64 + n]);
            g_W2fh[blk * 1024 + e] = v;
        }
    } else if (blk == KNB) {
        // W1 tf32 frags: [256][64], 32 kc8-steps x 8 nt
        for (int e = t; e < 8192; e += 256) {
            int lane = e & 31, nt = (e >> 5) & 7, kcg = e >> 8;
            int c0 = kcg * 8 + (lane & 3);
            int d  = nt * 8 + (lane >> 2);
            g_W1f[(kcg * 8 + nt) * 32 + lane] =
                make_float2(tf32r(__ldg(W1 + c0 * 64 + d)),
                            tf32r(__ldg(W1 + (c0 + 4) * 64 + d)));
        }
    } else {
        // W3 fp16 frags: [64][256], 4 kc16-steps x 32 nt
        for (int e = t; e < 4096; e += 256) {
            int lane = e & 31, nt = (e >> 5) & 31, kc = e >> 10;
            int qr = lane >> 2, ql = lane & 3;
            int n  = nt * 8 + qr;
            int c0 = kc * 16 + 2 * ql;
            uint2 v;
            v.x = packh(__ldg(W3 + c0 * 256 + n),       __ldg(W3 + (c0 + 1) * 256 + n));
            v.y = packh(__ldg(W3 + (c0 + 8) * 256 + n), __ldg(W3 + (c0 + 9) * 256 + n));
            g_W3fh[e] = v;
        }
    }
}

// ---------------------------------------------------------------------------
// Kernel A (tf32 tensor, 128 thr, 2 blocks/SM): h = relu(LN(feats @ W1)) -> fp16.
// Tile 128x64, K=256 in 4 chunks, cp.async double buffer (A + B frags).
// ---------------------------------------------------------------------------
__global__ void __launch_bounds__(128, 2) kA(const float* __restrict__ feats,
                                             const float* __restrict__ g1v,
                                             const float* __restrict__ b1v)
{
    extern __shared__ float sm[];
    float* As = sm;                  // 2 x [128][68]
    float* Bf = sm + 2 * KA_AS;      // 2 x [4096]

    const int t    = threadIdx.x;
    const int base = blockIdx.x * 128;
    const int lane = t & 31, w = t >> 5;
    const int qr = lane >> 2, ql = lane & 3;

    const unsigned As_s = (unsigned)__cvta_generic_to_shared(As);
    const unsigned Bf_s = (unsigned)__cvta_generic_to_shared(Bf);

    auto prefetch = [&](int ch, int buf) {
        const float4* bsrc = (const float4*)(g_W1f + ch * 2048);
        unsigned bb = Bf_s + buf * (KA_BS * 4);
#pragma unroll
        for (int i = 0; i < 8; i++) {
            int u = t + 128 * i;
            cp16(bb + u * 16, bsrc + u);
        }
        unsigned ab = As_s + buf * (KA_AS * 4);
#pragma unroll
        for (int i = 0; i < 16; i++) {
            int u = t + 128 * i;
            int r = u >> 4, c4 = u & 15;
            int gr = base + r; if (gr >= N_PTS) gr = N_PTS - 1;
            cp16(ab + (r * 68 + c4 * 4) * 4, feats + gr * CIN + ch * 64 + c4 * 4);
        }
        cp_commit();
    };

    float d[2][8][4];
#pragma unroll
    for (int mt = 0; mt < 2; mt++)
#pragma unroll
        for (int nt = 0; nt < 8; nt++)
#pragma unroll
            for (int p = 0; p < 4; p++) d[mt][nt][p] = 0.f;

    prefetch(0, 0);
    for (int ch = 0; ch < 4; ch++) {
        const int buf = ch & 1;
        if (ch < 3) { prefetch(ch + 1, buf ^ 1); cp_wait1(); } else cp_wait0();
        __syncthreads();

        const float*  Ab = As + buf * KA_AS;
        const float2* Bb = (const float2*)(Bf + buf * KA_BS);

#pragma unroll
        for (int kc = 0; kc < 8; kc++) {
            unsigned a[2][4];
#pragma unroll
            for (int mt = 0; mt < 2; mt++) {
                int r0 = w * 32 + mt * 16 + qr;
                int c0 = kc * 8 + ql;
                a[mt][0] = tf32b(Ab[r0 * 68 + c0]);
                a[mt][1] = tf32b(Ab[(r0 + 8) * 68 + c0]);
                a[mt][2] = tf32b(Ab[r0 * 68 + c0 + 4]);
                a[mt][3] = tf32b(Ab[(r0 + 8) * 68 + c0 + 4]);
            }
#pragma unroll
            for (int nt = 0; nt < 8; nt++) {
                float2 bv = Bb[(kc * 8 + nt) * 32 + lane];
                unsigned b[2] = {__float_as_uint(bv.x), __float_as_uint(bv.y)};
                mma_tf32(d[0][nt], a[0], b);
                mma_tf32(d[1][nt], a[1], b);
            }
        }
        __syncthreads();
    }

    float2 lg[8], lb[8];
#pragma unroll
    for (int nt = 0; nt < 8; nt++) {
        lg[nt] = __ldg((const float2*)(g1v + nt * 8 + 2 * ql));
        lb[nt] = __ldg((const float2*)(b1v + nt * 8 + 2 * ql));
    }

#pragma unroll
    for (int mt = 0; mt < 2; mt++) {
#pragma unroll
        for (int h = 0; h < 2; h++) {
            int row = w * 32 + mt * 16 + qr + 8 * h;
            float s = 0.f, q = 0.f;
#pragma unroll
            for (int nt = 0; nt < 8; nt++) {
                float v0 = d[mt][nt][2 * h], v1 = d[mt][nt][2 * h + 1];
                s += v0 + v1; q += v0 * v0 + v1 * v1;
            }
            s += __shfl_xor_sync(0xffffffffu, s, 1, 4);
            q += __shfl_xor_sync(0xffffffffu, q, 1, 4);
            s += __shfl_xor_sync(0xffffffffu, s, 2, 4);
            q += __shfl_xor_sync(0xffffffffu, q, 2, 4);
            float mu  = s * (1.f / 64.f);
            float var = q * (1.f / 64.f) - mu * mu;
            float inv = rsqrtf(var + LN_EPS);

            __half* dst = g_h + (base + row) * CMID + 2 * ql;   // padded
#pragma unroll
            for (int nt = 0; nt < 8; nt++) {
                float ox = fmaxf((d[mt][nt][2 * h]     - mu) * inv * lg[nt].x + lb[nt].x, 0.f);
                float oy = fmaxf((d[mt][nt][2 * h + 1] - mu) * inv * lg[nt].y + lb[nt].y, 0.f);
                *(__half2*)(dst + nt * 8) = __floats2half2_rn(ox, oy);
            }
        }
    }
}

// ---------------------------------------------------------------------------
// Kernel B (fp16 tensor, 128 thr, 3 blocks/SM): h2 = relu(LN(sum_k gather @ W2[k])).
// Tile 128 rows, 27 k-steps, cp.async double buffer. Warp: 32 rows x 64 cols,
// 4 kc16-steps x (2mt x 8nt) m16n8k16. A smem u32 stride 36 (conflict-free).
// ---------------------------------------------------------------------------
__global__ void __launch_bounds__(128, 3) kB(const int*   __restrict__ nidx,
                                             const float* __restrict__ g2v,
                                             const float* __restrict__ b2v)
{
    extern __shared__ unsigned smu[];
    unsigned* As = smu;                   // 2 x [128][36] u32
    unsigned* Bf = smu + 2 * KB_AW;       // 2 x [2048] u32 (uint2[1024])

    const int t    = threadIdx.x;
    const int base = blockIdx.x * 128;
    const int lane = t & 31, w = t >> 5;
    const int qr = lane >> 2, ql = lane & 3;

    const unsigned As_s = (unsigned)__cvta_generic_to_shared(As);
    const unsigned Bf_s = (unsigned)__cvta_generic_to_shared(Bf);

    auto prefetch = [&](int k, int buf) {
        const uint2* bsrc = g_W2fh + k * 1024;       // 8KB
        unsigned bb = Bf_s + buf * (KB_BW * 4);
#pragma unroll
        for (int i = 0; i < 4; i++) {
            int u = t + 128 * i;                     // 512 chunks of 16B
            cp16(bb + u * 16, (const char*)bsrc + u * 16);
        }
        unsigned ab = As_s + buf * (KB_AW * 4);
#pragma unroll
        for (int i = 0; i < 8; i++) {
            int u = t + 128 * i;                     // 128 rows x 8 chunks
            int r = u >> 3, c8 = u & 7;
            int gr = base + r;
            int src = (gr < N_PTS) ? __ldg(nidx + gr * KNB + k) : 0;
            cp16(ab + (r * 36 + c8 * 4) * 4, g_h + src * CMID + c8 * 8);
        }
        cp_commit();
    };

    float d[2][8][4];
#pragma unroll
    for (int mt = 0; mt < 2; mt++)
#pragma unroll
        for (int nt = 0; nt < 8; nt++)
#pragma unroll
            for (int p = 0; p < 4; p++) d[mt][nt][p] = 0.f;

    prefetch(0, 0);
    for (int k = 0; k < KNB; k++) {
        const int buf = k & 1;
        if (k < KNB - 1) { prefetch(k + 1, buf ^ 1); cp_wait1(); } else cp_wait0();
        __syncthreads();

        const unsigned* Ab = As + buf * KB_AW;
        const uint2*    Bb = (const uint2*)(Bf + buf * KB_BW);

#pragma unroll
        for (int kc = 0; kc < 4; kc++) {
            unsigned a[2][4];
#pragma unroll
            for (int mt = 0; mt < 2; mt++) {
                int r0 = w * 32 + mt * 16 + qr;
                int c0 = kc * 8 + ql;
                a[mt][0] = Ab[r0 * 36 + c0];
                a[mt][1] = Ab[(r0 + 8) * 36 + c0];
                a[mt][2] = Ab[r0 * 36 + c0 + 4];
                a[mt][3] = Ab[(r0 + 8) * 36 + c0 + 4];
            }
#pragma unroll
            for (int nt = 0; nt < 8; nt++) {
                uint2 bv = Bb[(kc * 8 + nt) * 32 + lane];
                unsigned b[2] = {bv.x, bv.y};
                mma_f16(d[0][nt], a[0], b);
                mma_f16(d[1][nt], a[1], b);
            }
        }
        __syncthreads();
    }

    float2 lg[8], lb[8];
#pragma unroll
    for (int nt = 0; nt < 8; nt++) {
        lg[nt] = __ldg((const float2*)(g2v + nt * 8 + 2 * ql));
        lb[nt] = __ldg((const float2*)(b2v + nt * 8 + 2 * ql));
    }

#pragma unroll
    for (int mt = 0; mt < 2; mt++) {
#pragma unroll
        for (int h = 0; h < 2; h++) {
            int row = w * 32 + mt * 16 + qr + 8 * h;
            float s = 0.f, q = 0.f;
#pragma unroll
            for (int nt = 0; nt < 8; nt++) {
                float v0 = d[mt][nt][2 * h], v1 = d[mt][nt][2 * h + 1];
                s += v0 + v1; q += v0 * v0 + v1 * v1;
            }
            s += __shfl_xor_sync(0xffffffffu, s, 1, 4);
            q += __shfl_xor_sync(0xffffffffu, q, 1, 4);
            s += __shfl_xor_sync(0xffffffffu, s, 2, 4);
            q += __shfl_xor_sync(0xffffffffu, q, 2, 4);
            float mu  = s * (1.f / 64.f);
            float var = q * (1.f / 64.f) - mu * mu;
            float inv = rsqrtf(var + LN_EPS);

            __half* dst = g_h2 + (base + row) * CMID + 2 * ql;   // padded
#pragma unroll
            for (int nt = 0; nt < 8; nt++) {
                float ox = fmaxf((d[mt][nt][2 * h]     - mu) * inv * lg[nt].x + lb[nt].x, 0.f);
                float oy = fmaxf((d[mt][nt][2 * h + 1] - mu) * inv * lg[nt].y + lb[nt].y, 0.f);
                *(__half2*)(dst + nt * 8) = __floats2half2_rn(ox, oy);
            }
        }
    }
}

// ---------------------------------------------------------------------------
// Kernel C (fp16 tensor, PERSISTENT, 256 thr, 2 blocks/SM):
// out = relu(LN(h2 @ W3) + feats). Grid 296; W3 frags (32KB) staged once;
// 64-row tiles, cp.async double-buffered A. 4 kc16-steps.
// ---------------------------------------------------------------------------
__global__ void __launch_bounds__(256, 2) kC(const float* __restrict__ feats,
                                             const float* __restrict__ g3v,
                                             const float* __restrict__ b3v,
                                             float* __restrict__ out)
{
    extern __shared__ unsigned smu[];
    unsigned* As = smu;                        // 2 x [64][36] u32
    unsigned* Bs = smu + 2 * KC_AW;            // [8192] u32 = uint2[4096], 32KB
    float2*  red = (float2*)(Bs + 8192);       // [64][4]

    const int t    = threadIdx.x;
    const int lane = t & 31, w = t >> 5;
    const int wr = w >> 2, wc = w & 3;
    const int qr = lane >> 2, ql = lane & 3;

    const unsigned As_s = (unsigned)__cvta_generic_to_shared(As);

    // Stage W3 frags once (2048 chunks of 16B)
#pragma unroll
    for (int i = 0; i < 8; i++) {
        int u = t + 256 * i;
        *(uint4*)(Bs + u * 4) = __ldg((const uint4*)g_W3fh + u);
    }

    auto prefetchA = [&](int tile, int buf) {
        unsigned ab = As_s + buf * (KC_AW * 4);
        const __half* src = g_h2 + tile * 64 * CMID;   // padded
#pragma unroll
        for (int i = 0; i < 2; i++) {
            int u = t + 256 * i;                       // 64 rows x 8 chunks
            int r = u >> 3, c8 = u & 7;
            cp16(ab + (r * 36 + c8 * 4) * 4, src + r * CMID + c8 * 8);
        }
        cp_commit();
    };

    float2 lg[8], lb[8];
#pragma unroll
    for (int nt = 0; nt < 8; nt++) {
        lg[nt] = __ldg((const float2*)(g3v + wc * 64 + nt * 8 + 2 * ql));
        lb[nt] = __ldg((const float2*)(b3v + wc * 64 + nt * 8 + 2 * ql));
    }

    int tile = blockIdx.x;
    prefetchA(tile, 0);
    int it = 0;
    for (; tile < KC_TILES; tile += KC_GRID, it++) {
        const int buf  = it & 1;
        const int base = tile * 64;
        int ntile = tile + KC_GRID;
        if (ntile < KC_TILES) { prefetchA(ntile, buf ^ 1); cp_wait1(); } else cp_wait0();
        __syncthreads();

        const unsigned* Ab = As + buf * KC_AW;
        const uint2*    Bb = (const uint2*)Bs;

        float d[2][8][4];
#pragma unroll
        for (int mt = 0; mt < 2; mt++)
#pragma unroll
            for (int nt = 0; nt < 8; nt++)
#pragma unroll
                for (int p = 0; p < 4; p++) d[mt][nt][p] = 0.f;

#pragma unroll
        for (int kc = 0; kc < 4; kc++) {
            unsigned a[2][4];
#pragma unroll
            for (int mt = 0; mt < 2; mt++) {
                int r0 = wr * 32 + mt * 16 + qr;
                int c0 = kc * 8 + ql;
                a[mt][0] = Ab[r0 * 36 + c0];
                a[mt][1] = Ab[(r0 + 8) * 36 + c0];
                a[mt][2] = Ab[r0 * 36 + c0 + 4];
                a[mt][3] = Ab[(r0 + 8) * 36 + c0 + 4];
            }
#pragma unroll
            for (int nt = 0; nt < 8; nt++) {
                uint2 bv = Bb[(kc * 32 + wc * 8 + nt) * 32 + lane];
                unsigned b[2] = {bv.x, bv.y};
                mma_f16(d[0][nt], a[0], b);
                mma_f16(d[1][nt], a[1], b);
            }
        }

        // LN over 256 cols: quad partials -> red[64][4] -> combine
#pragma unroll
        for (int mt = 0; mt < 2; mt++) {
#pragma unroll
            for (int h = 0; h < 2; h++) {
                int row = wr * 32 + mt * 16 + qr + 8 * h;
                float s = 0.f, q = 0.f;
#pragma unroll
                for (int nt = 0; nt < 8; nt++) {
                    float v0 = d[mt][nt][2 * h], v1 = d[mt][nt][2 * h + 1];
                    s += v0 + v1; q += v0 * v0 + v1 * v1;
                }
                s += __shfl_xor_sync(0xffffffffu, s, 1, 4);
                q += __shfl_xor_sync(0xffffffffu, q, 1, 4);
                s += __shfl_xor_sync(0xffffffffu, s, 2, 4);
                q += __shfl_xor_sync(0xffffffffu, q, 2, 4);
                if (ql == 0) red[row * 4 + wc] = make_float2(s, q);
            }
        }
        __syncthreads();

#pragma unroll
        for (int mt = 0; mt < 2; mt++) {
#pragma unroll
            for (int h = 0; h < 2; h++) {
                int row  = wr * 32 + mt * 16 + qr + 8 * h;
                int grow = base + row;
                float2 p0 = red[row * 4 + 0], p1 = red[row * 4 + 1];
                float2 p2 = red[row * 4 + 2], p3 = red[row * 4 + 3];
                float S = p0.x + p1.x + p2.x + p3.x;
                float Q = p0.y + p1.y + p2.y + p3.y;
                float mu  = S * (1.f / 256.f);
                float var = Q * (1.f / 256.f) - mu * mu;
                float inv = rsqrtf(var + LN_EPS);

                if (grow < N_PTS) {
                    const float* fsrc = feats + grow * CIN + wc * 64 + 2 * ql;
                    float* dst = out + grow * COUT + wc * 64 + 2 * ql;
#pragma unroll
                    for (int nt = 0; nt < 8; nt++) {
                        float2 r4 = __ldg((const float2*)(fsrc + nt * 8));
                        float2 o;
                        o.x = fmaxf((d[mt][nt][2 * h]     - mu) * inv * lg[nt].x + lb[nt].x + r4.x, 0.f);
                        o.y = fmaxf((d[mt][nt][2 * h + 1] - mu) * inv * lg[nt].y + lb[nt].y + r4.y, 0.f);
                        *(float2*)(dst + nt * 8) = o;
                    }
                }
            }
        }
    }
}

// ---------------------------------------------------------------------------
extern "C" void kernel_launch(void* const* d_in, const int* in_sizes, int n_in,
                              void* d_out, int out_size)
{
    const float* feats = (const float*)d_in[0];
    const int*   nidx  = (const int*)  d_in[1];
    const float* W1    = (const float*)d_in[2];
    const float* g1    = (const float*)d_in[3];
    const float* b1    = (const float*)d_in[4];
    const float* W2    = (const float*)d_in[5];
    const float* g2    = (const float*)d_in[6];
    const float* b2    = (const float*)d_in[7];
    const float* W3    = (const float*)d_in[8];
    const float* g3    = (const float*)d_in[9];
    const float* b3    = (const float*)d_in[10];
    float* out = (float*)d_out;

    cudaFuncSetAttribute(kA, cudaFuncAttributeMaxDynamicSharedMemorySize, SMEM_A);
    cudaFuncSetAttribute(kB, cudaFuncAttributeMaxDynamicSharedMemorySize, SMEM_B);
    cudaFuncSetAttribute(kC, cudaFuncAttributeMaxDynamicSharedMemorySize, SMEM_C);

    kPrep<<<KNB + 2, 256>>>(W1, W2, W3);
    kA<<<N_PAD / 128, 128, SMEM_A>>>(feats, g1, b1);
    kB<<<N_PAD / 128, 128, SMEM_B>>>(nidx, g2, b2);
    kC<<<KC_GRID, 256, SMEM_C>>>(feats, g3, b3, out);
}